// round 14
// baseline (speedup 1.0000x reference)
#include <cuda_runtime.h>
#include <cuda_bf16.h>
#include <math.h>
#include <stdint.h>

#define NNODES 50000
#define NEDGES 800000
#define NGRAPH 512
#define MAXF   512
#define KDIM   256

// weight buffer layout (elements): head Wo^T at 0 (2048*1024),
// W1^T at WOFF1 (256*256), W2^T at WOFF2, W3^T at WOFF3 (512*256)
#define WOFF0 0
#define WOFF1 (2048 * 1024)
#define WOFF2 (WOFF1 + 256 * 256)
#define WOFF3 (WOFF2 + 256 * 256)
#define WTOT  (WOFF3 + 512 * 256)

// ---- scratch (device globals; no allocation allowed) ----
__device__ float g_x [NNODES * MAXF];       // activations (GEMM epilogue output)
__device__ int   g_deg[NNODES];
__device__ float g_dis[NNODES];
__device__ int   g_rowstart[NNODES];
__device__ int   g_cursor[NNODES];
__device__ int   g_csr[NEDGES];
__device__ float g_wgate[NNODES];
__device__ int   g_tsum[1024];
__device__ int   g_gstart[NGRAPH + 1];
// bf16 split operands for GEMMs (A operand rows; also holds pooled feats for head)
__device__ __nv_bfloat16 g_ahi[NNODES * KDIM];
__device__ __nv_bfloat16 g_alo[NNODES * KDIM];
__device__ __nv_bfloat16 g_wthi[WTOT];
__device__ __nv_bfloat16 g_wtlo[WTOT];

__device__ __forceinline__ uint32_t smem_u32(const void* p) {
    uint32_t a;
    asm("{ .reg .u64 t; cvta.to.shared.u64 t, %1; cvt.u32.u64 %0, t; }"
        : "=r"(a) : "l"(p));
    return a;
}

#define LDSM4(R, addr)                                                          \
    asm volatile("ldmatrix.sync.aligned.m8n8.x4.shared.b16 {%0,%1,%2,%3}, [%4];" \
                 : "=r"((R)[0]), "=r"((R)[1]), "=r"((R)[2]), "=r"((R)[3])        \
                 : "r"(addr))

#define MMA_BF16(C, A, B0, B1)                                                  \
    asm volatile(                                                               \
        "mma.sync.aligned.m16n8k16.row.col.f32.bf16.bf16.f32 "                  \
        "{%0,%1,%2,%3}, {%4,%5,%6,%7}, {%8,%9}, {%0,%1,%2,%3};"                 \
        : "+f"((C)[0]), "+f"((C)[1]), "+f"((C)[2]), "+f"((C)[3])                \
        : "r"((A)[0]), "r"((A)[1]), "r"((A)[2]), "r"((A)[3]), "r"(B0), "r"(B1))

#define CP16(dst, src, sz)                                                      \
    asm volatile("cp.async.cg.shared.global [%0], [%1], 16, %2;"                \
                 :: "r"(dst), "l"(src), "r"(sz))
#define CP_COMMIT() asm volatile("cp.async.commit_group;" ::: "memory")
#define CP_WAIT(n)  asm volatile("cp.async.wait_group %0;" :: "n"(n) : "memory")

// ================= graph structure build =================
__global__ void k_zero() {
    for (int i = blockIdx.x * blockDim.x + threadIdx.x; i < NNODES;
         i += gridDim.x * blockDim.x) {
        g_deg[i] = 0;
        g_cursor[i] = 0;
    }
}
__global__ void k_deg(const int* __restrict__ ei) {
    for (int e = blockIdx.x * blockDim.x + threadIdx.x; e < NEDGES;
         e += gridDim.x * blockDim.x) {
        int d = ei[NEDGES + e];
        if (d >= 0 && d < NNODES) atomicAdd(&g_deg[d], 1);
    }
}
__global__ void k_dis() {
    int n = blockIdx.x * blockDim.x + threadIdx.x;
    if (n < NNODES) g_dis[n] = rsqrtf((float)(g_deg[n] + 1));
}
__global__ void k_scan1() {
    int t = blockIdx.x * blockDim.x + threadIdx.x;
    const int chunk = (NNODES + 1023) / 1024;
    int base = t * chunk, s = 0;
    for (int i = 0; i < chunk; i++) {
        int n = base + i;
        if (n < NNODES) s += g_deg[n];
    }
    g_tsum[t] = s;
}
__global__ void k_scan2() {
    __shared__ int sh[1024];
    int t = threadIdx.x;
    sh[t] = g_tsum[t];
    __syncthreads();
    for (int off = 1; off < 1024; off <<= 1) {
        int v = (t >= off) ? sh[t - off] : 0;
        __syncthreads();
        sh[t] += v;
        __syncthreads();
    }
    g_tsum[t] = (t == 0) ? 0 : sh[t - 1];
}
__global__ void k_scan3() {
    int t = blockIdx.x * blockDim.x + threadIdx.x;
    const int chunk = (NNODES + 1023) / 1024;
    int base = t * chunk, off = g_tsum[t];
    for (int i = 0; i < chunk; i++) {
        int n = base + i;
        if (n < NNODES) {
            g_rowstart[n] = off;
            off += g_deg[n];
        }
    }
}
__global__ void k_csr(const int* __restrict__ ei) {
    for (int e = blockIdx.x * blockDim.x + threadIdx.x; e < NEDGES;
         e += gridDim.x * blockDim.x) {
        int s = ei[e];
        int d = ei[NEDGES + e];
        if (s < 0 || s >= NNODES || d < 0 || d >= NNODES) continue;
        int pos = g_rowstart[d] + atomicAdd(&g_cursor[d], 1);
        if (pos >= 0 && pos < NEDGES) g_csr[pos] = s;
    }
}

// ---- W[K, Nn] (row-major) -> W^T split [Nn, K] at dstOff, tiled transpose ----
__global__ void k_cvtwT(const float* __restrict__ W, int Nn, int K, int dstOff) {
    __shared__ float ts[64][65];
    const int tid = threadIdx.x;
    const int n0 = blockIdx.x * 64, k0 = blockIdx.y * 64;
#pragma unroll
    for (int i = 0; i < 16; i++) {
        int idx = tid + i * 256;
        int r = idx >> 6, c = idx & 63;
        ts[r][c] = W[(size_t)(k0 + r) * Nn + n0 + c];
    }
    __syncthreads();
#pragma unroll
    for (int i = 0; i < 8; i++) {
        int idx = tid + i * 256;
        int r = idx >> 5, c2 = (idx & 31) * 2;
        float x0 = ts[c2][r], x1 = ts[c2 + 1][r];
        __nv_bfloat16 h0 = __float2bfloat16(x0);
        __nv_bfloat16 h1 = __float2bfloat16(x1);
        __nv_bfloat16 l0 = __float2bfloat16(x0 - __bfloat162float(h0));
        __nv_bfloat16 l1 = __float2bfloat16(x1 - __bfloat162float(h1));
        size_t off = (size_t)dstOff + (size_t)(n0 + r) * K + k0 + c2;
        uint16_t a0 = *(uint16_t*)&h0, a1 = *(uint16_t*)&h1;
        uint16_t b0 = *(uint16_t*)&l0, b1 = *(uint16_t*)&l1;
        *(uint32_t*)&g_wthi[off] = (uint32_t)a0 | ((uint32_t)a1 << 16);
        *(uint32_t*)&g_wtlo[off] = (uint32_t)b0 | ((uint32_t)b1 << 16);
    }
}

// ---- pre-aggregation: y[d] = dis[d] * sum_{s in N(d)+{d}} x[s]*dis[s]
template <int ASEL>
__global__ void k_aggpre(const float* __restrict__ xext) {
    const float* __restrict__ x = (ASEL == 0) ? xext : (const float*)g_x;
    int d = blockIdx.x;
    int f = threadIdx.x;  // 256
    float dd = g_dis[d];
    float acc = x[(size_t)d * KDIM + f] * dd;
    int p0 = g_rowstart[d], cnt = g_deg[d];
    int j = 0;
    for (; j + 4 <= cnt; j += 4) {
        int s0 = g_csr[p0 + j],     s1 = g_csr[p0 + j + 1];
        int s2 = g_csr[p0 + j + 2], s3 = g_csr[p0 + j + 3];
        float v0 = x[(size_t)s0 * KDIM + f];
        float v1 = x[(size_t)s1 * KDIM + f];
        float v2 = x[(size_t)s2 * KDIM + f];
        float v3 = x[(size_t)s3 * KDIM + f];
        acc += v0 * g_dis[s0] + v1 * g_dis[s1] + v2 * g_dis[s2] + v3 * g_dis[s3];
    }
    for (; j < cnt; j++) {
        int s = g_csr[p0 + j];
        acc += x[(size_t)s * KDIM + f] * g_dis[s];
    }
    float y = acc * dd;
    __nv_bfloat16 h = __float2bfloat16(y);
    g_ahi[(size_t)d * KDIM + f] = h;
    g_alo[(size_t)d * KDIM + f] = __float2bfloat16(y - __bfloat162float(h));
}

// ================= split-bf16 mma.sync GEMM, 128x128 tile, cp.async 2-stage ===
// C[M, Nn] = relu( (A @ W) + bias ),  A split [M,K] in g_ahi/g_alo,
// W^T split [Nn,K] at g_wthi+wOff / g_wtlo+wOff.  CSEL: 0 = Cout arg, 1 = g_x.
// Inner loop processes one B-subtile at a time to keep live regs < 128.
#define STG_SZ 32768
#define OB     16384
template <int CSEL>
__global__ __launch_bounds__(256, 2) void k_mmagemm(float* __restrict__ Cout,
                                                    int M, int Nn, int K, int wOff,
                                                    const float* __restrict__ bias) {
    extern __shared__ __align__(16) char sm[];     // 2 * STG_SZ
    float* __restrict__ C = (CSEL == 0) ? Cout : (float*)g_x;
    const int tid = threadIdx.x, wid = tid >> 5, lane = tid & 31;
    const int wm = wid & 3, wn = wid >> 2;    // 4 x 2 warps, warp tile 32 x 64
    const int bm = blockIdx.x * 128, nb = blockIdx.y * 128;
    const uint32_t sb = smem_u32(sm);

    const int a_row = wm * 32 + (lane & 7) + ((lane >> 3) & 1) * 8;
    const int a_c   = (lane >> 4) & 1;
    const int b_row = wn * 64 + (lane & 7) + ((lane >> 4) & 1) * 8;
    const int b_c   = (lane >> 3) & 1;

    float acc[2][8][4];
#pragma unroll
    for (int mt = 0; mt < 2; mt++)
#pragma unroll
        for (int nt = 0; nt < 8; nt++)
#pragma unroll
            for (int i = 0; i < 4; i++) acc[mt][nt][i] = 0.f;

    auto load_stage = [&](int kc, int s) {
        uint32_t base = sb + s * STG_SZ;
#pragma unroll
        for (int i = 0; i < 4; i++) {
            int idx = tid + i * 256;
            int r = idx >> 3, cc = idx & 7;
            int grow = bm + r;
            int ok = (grow < M);
            int grc = ok ? grow : (M - 1);
            const __nv_bfloat16* src = (cc < 4)
                ? &g_ahi[(size_t)grc * K + kc * 32 + cc * 8]
                : &g_alo[(size_t)grc * K + kc * 32 + (cc - 4) * 8];
            uint32_t dst = base + (r << 7) + ((cc ^ (r & 7)) << 4);
            CP16(dst, src, ok ? 16 : 0);
        }
#pragma unroll
        for (int i = 0; i < 4; i++) {
            int idx = tid + i * 256;
            int r = idx >> 3, cc = idx & 7;
            const __nv_bfloat16* src = (cc < 4)
                ? &g_wthi[(size_t)wOff + (size_t)(nb + r) * K + kc * 32 + cc * 8]
                : &g_wtlo[(size_t)wOff + (size_t)(nb + r) * K + kc * 32 + (cc - 4) * 8];
            uint32_t dst = base + OB + (r << 7) + ((cc ^ (r & 7)) << 4);
            CP16(dst, src, 16);
        }
    };

    load_stage(0, 0);
    CP_COMMIT();

    const int NKC = K / 32;
    for (int kc = 0; kc < NKC; kc++) {
        int s = kc & 1;
        if (kc + 1 < NKC) {
            load_stage(kc + 1, s ^ 1);
            CP_COMMIT();
            CP_WAIT(1);
        } else {
            CP_WAIT(0);
        }
        __syncthreads();

        uint32_t stg = sb + s * STG_SZ;
#pragma unroll
        for (int ks = 0; ks < 2; ks++) {
            uint32_t ah[2][4], al[2][4];
            int ach = ks * 2 + a_c;
            int bch = ks * 2 + b_c;
#pragma unroll
            for (int mt = 0; mt < 2; mt++) {
                int row = a_row + mt * 16;
                uint32_t rb_ = stg + (row << 7);
                LDSM4(ah[mt], rb_ + ((ach ^ (row & 7)) << 4));
                LDSM4(al[mt], rb_ + (((ach + 4) ^ (row & 7)) << 4));
            }
            // one B-subtile at a time: live B regs = 4 (bb reused hi->lo)
#pragma unroll
            for (int p = 0; p < 4; p++) {
                int row = b_row + p * 16;
                uint32_t rb_ = stg + OB + (row << 7);
                {
                    uint32_t bb[4];
                    LDSM4(bb, rb_ + ((bch ^ (row & 7)) << 4));   // hi
#pragma unroll
                    for (int mt = 0; mt < 2; mt++)
#pragma unroll
                        for (int h = 0; h < 2; h++) {
                            MMA_BF16(acc[mt][p * 2 + h], ah[mt], bb[h * 2], bb[h * 2 + 1]);
                            MMA_BF16(acc[mt][p * 2 + h], al[mt], bb[h * 2], bb[h * 2 + 1]);
                        }
                }
                {
                    uint32_t bb[4];
                    LDSM4(bb, rb_ + (((bch + 4) ^ (row & 7)) << 4)); // lo
#pragma unroll
                    for (int mt = 0; mt < 2; mt++)
#pragma unroll
                        for (int h = 0; h < 2; h++)
                            MMA_BF16(acc[mt][p * 2 + h], ah[mt], bb[h * 2], bb[h * 2 + 1]);
                }
            }
        }
        __syncthreads();
    }

    // ---- epilogue: + bias, relu, store fp32 ----
#pragma unroll
    for (int mt = 0; mt < 2; mt++) {
        int r0 = bm + wm * 32 + mt * 16 + (lane >> 2);
        int r1 = r0 + 8;
#pragma unroll
        for (int nt = 0; nt < 8; nt++) {
            int col = nb + wn * 64 + nt * 8 + (lane & 3) * 2;
            float bb0 = bias[col], bb1 = bias[col + 1];
            if (r0 < M) {
                float2 v = make_float2(fmaxf(acc[mt][nt][0] + bb0, 0.f),
                                       fmaxf(acc[mt][nt][1] + bb1, 0.f));
                *(float2*)&C[(size_t)r0 * Nn + col] = v;
            }
            if (r1 < M) {
                float2 v = make_float2(fmaxf(acc[mt][nt][2] + bb0, 0.f),
                                       fmaxf(acc[mt][nt][3] + bb1, 0.f));
                *(float2*)&C[(size_t)r1 * Nn + col] = v;
            }
        }
    }
}

// ================= pooling =================
__global__ void k_gate(const float* __restrict__ pw, const float* __restrict__ pb) {
    int warp = (blockIdx.x * blockDim.x + threadIdx.x) >> 5;
    int lane = threadIdx.x & 31;
    if (warp >= NNODES) return;
    const float* row = &g_x[(size_t)warp * 512];
    float s = 0.f;
#pragma unroll 4
    for (int i = lane; i < 512; i += 32) s += row[i] * pw[i];
#pragma unroll
    for (int o = 16; o; o >>= 1) s += __shfl_xor_sync(0xFFFFFFFFu, s, o);
    if (lane == 0) g_wgate[warp] = 1.f / (1.f + expf(-(s + pb[0])));
}

__global__ void k_gstart(const int* __restrict__ batch) {
    for (int n = blockIdx.x * blockDim.x + threadIdx.x; n < NNODES;
         n += gridDim.x * blockDim.x) {
        int b = batch[n];
        if (b < 0) b = 0;
        if (b >= NGRAPH) b = NGRAPH - 1;
        int prev = -1;
        if (n) {
            prev = batch[n - 1];
            if (prev < 0) prev = 0;
            if (prev >= NGRAPH) prev = NGRAPH - 1;
        }
        for (int g = prev + 1; g <= b; g++) g_gstart[g] = n;
        if (n == NNODES - 1)
            for (int g = b + 1; g <= NGRAPH; g++) g_gstart[g] = NNODES;
    }
}

// pool writes the head GEMM A operand (bf16 hi/lo split, row g, K=1024)
__global__ void k_pool() {
    int g = blockIdx.x;
    int f = threadIdx.x;  // 256
    int s = g_gstart[g], e = g_gstart[g + 1];
    float ws0 = 0.f, ws1 = 0.f, mx0 = 0.f, mx1 = 0.f;
    for (int n = s; n < e; n++) {
        float w = g_wgate[n];
        float v0 = g_x[(size_t)n * 512 + f];
        float v1 = g_x[(size_t)n * 512 + f + 256];
        ws0 += v0 * w;
        ws1 += v1 * w;
        mx0 = fmaxf(mx0, v0);
        mx1 = fmaxf(mx1, v1);
    }
    size_t base = (size_t)g * 1024;
    float vs[4] = {ws0, ws1, mx0, mx1};
    int   cs[4] = {f, f + 256, 512 + f, 768 + f};
#pragma unroll
    for (int i = 0; i < 4; i++) {
        __nv_bfloat16 h = __float2bfloat16(vs[i]);
        g_ahi[base + cs[i]] = h;
        g_alo[base + cs[i]] = __float2bfloat16(vs[i] - __bfloat162float(h));
    }
}

extern "C" void kernel_launch(void* const* d_in, const int* in_sizes, int n_in,
                              void* d_out, int out_size) {
    const float* xin   = (const float*)d_in[0];
    const int*   ei    = (const int*)d_in[1];
    const int*   batch = (const int*)d_in[2];
    const float* W1 = (const float*)d_in[3];
    const float* b1 = (const float*)d_in[4];
    const float* W2 = (const float*)d_in[5];
    const float* b2 = (const float*)d_in[6];
    const float* W3 = (const float*)d_in[7];
    const float* b3 = (const float*)d_in[8];
    const float* pw = (const float*)d_in[9];
    const float* pb = (const float*)d_in[10];
    const float* Wo = (const float*)d_in[11];
    const float* bo = (const float*)d_in[12];
    float* out = (float*)d_out;

    cudaFuncSetAttribute(k_mmagemm<0>, cudaFuncAttributeMaxDynamicSharedMemorySize,
                         2 * STG_SZ);
    cudaFuncSetAttribute(k_mmagemm<1>, cudaFuncAttributeMaxDynamicSharedMemorySize,
                         2 * STG_SZ);

    // graph structure + all weight conversions (off the activation chain)
    k_zero<<<196, 256>>>();
    k_deg<<<512, 256>>>(ei);
    k_cvtwT<<<dim3(4, 4), 256>>>(W1, 256, KDIM, WOFF1);
    k_cvtwT<<<dim3(4, 4), 256>>>(W2, 256, KDIM, WOFF2);
    k_cvtwT<<<dim3(8, 4), 256>>>(W3, 512, KDIM, WOFF3);
    k_cvtwT<<<dim3(32, 16), 256>>>(Wo, 2048, 1024, WOFF0);
    k_dis<<<(NNODES + 255) / 256, 256>>>();
    k_scan1<<<4, 256>>>();
    k_scan2<<<1, 1024>>>();
    k_scan3<<<4, 256>>>();
    k_csr<<<512, 256>>>(ei);

    const int MBLK = (NNODES + 127) / 128;  // 391

    // layer 1
    k_aggpre<0><<<NNODES, 256>>>(xin);
    k_mmagemm<1><<<dim3(MBLK, 2), 256, 2 * STG_SZ>>>(nullptr, NNODES, 256, KDIM,
                                                     WOFF1, b1);
    // layer 2
    k_aggpre<1><<<NNODES, 256>>>(nullptr);
    k_mmagemm<1><<<dim3(MBLK, 2), 256, 2 * STG_SZ>>>(nullptr, NNODES, 256, KDIM,
                                                     WOFF2, b2);
    // layer 3
    k_aggpre<1><<<NNODES, 256>>>(nullptr);
    k_mmagemm<1><<<dim3(MBLK, 4), 256, 2 * STG_SZ>>>(nullptr, NNODES, 512, KDIM,
                                                     WOFF3, b3);

    // pooling (k_pool emits head A operand split)
    k_gate<<<(NNODES + 7) / 8, 256>>>(pw, pb);
    k_gstart<<<196, 256>>>(batch);
    k_pool<<<NGRAPH, 256>>>();

    // head: [512,1024] @ [1024,2048] + bias, relu -> out
    k_mmagemm<0><<<dim3(4, 16), 256, 2 * STG_SZ>>>(out, NGRAPH, 2048, 1024,
                                                   WOFF0, bo);
}

// round 16
// speedup vs baseline: 1.1668x; 1.1668x over previous
#include <cuda_runtime.h>
#include <cuda_bf16.h>
#include <math.h>
#include <stdint.h>

#define NNODES 50000
#define NEDGES 800000
#define NGRAPH 512
#define MAXF   512
#define KDIM   256

#define WOFF0 0
#define WOFF1 (2048 * 1024)
#define WOFF2 (WOFF1 + 256 * 256)
#define WOFF3 (WOFF2 + 256 * 256)
#define WTOT  (WOFF3 + 512 * 256)

// ---- scratch (device globals; no allocation allowed) ----
__device__ float g_x [NNODES * MAXF];
__device__ int   g_deg[NNODES];
__device__ float g_dis[NNODES];
__device__ int   g_rowstart[NNODES];
__device__ int   g_cursor[NNODES];
__device__ int   g_csr[NEDGES];
__device__ int   g_tsum[1024];
__device__ int   g_gstart[NGRAPH + 1];
__device__ __nv_bfloat16 g_ahi[NNODES * KDIM];
__device__ __nv_bfloat16 g_alo[NNODES * KDIM];
__device__ __nv_bfloat16 g_wthi[WTOT];
__device__ __nv_bfloat16 g_wtlo[WTOT];

__device__ __forceinline__ uint32_t smem_u32(const void* p) {
    uint32_t a;
    asm("{ .reg .u64 t; cvta.to.shared.u64 t, %1; cvt.u32.u64 %0, t; }"
        : "=r"(a) : "l"(p));
    return a;
}

#define LDSM4(R, addr)                                                          \
    asm volatile("ldmatrix.sync.aligned.m8n8.x4.shared.b16 {%0,%1,%2,%3}, [%4];" \
                 : "=r"((R)[0]), "=r"((R)[1]), "=r"((R)[2]), "=r"((R)[3])        \
                 : "r"(addr))

#define MMA_BF16(C, A, B0, B1)                                                  \
    asm volatile(                                                               \
        "mma.sync.aligned.m16n8k16.row.col.f32.bf16.bf16.f32 "                  \
        "{%0,%1,%2,%3}, {%4,%5,%6,%7}, {%8,%9}, {%0,%1,%2,%3};"                 \
        : "+f"((C)[0]), "+f"((C)[1]), "+f"((C)[2]), "+f"((C)[3])                \
        : "r"((A)[0]), "r"((A)[1]), "r"((A)[2]), "r"((A)[3]), "r"(B0), "r"(B1))

#define CP16(dst, src, sz)                                                      \
    asm volatile("cp.async.cg.shared.global [%0], [%1], 16, %2;"                \
                 :: "r"(dst), "l"(src), "r"(sz))
#define CP_COMMIT() asm volatile("cp.async.commit_group;" ::: "memory")
#define CP_WAIT(n)  asm volatile("cp.async.wait_group %0;" :: "n"(n) : "memory")

// ================= graph structure build =================
__global__ void k_zero() {
    for (int i = blockIdx.x * blockDim.x + threadIdx.x; i < NNODES;
         i += gridDim.x * blockDim.x) {
        g_deg[i] = 0;
        g_cursor[i] = 0;
    }
}
__global__ void k_deg(const int* __restrict__ ei) {
    for (int e = blockIdx.x * blockDim.x + threadIdx.x; e < NEDGES;
         e += gridDim.x * blockDim.x) {
        int d = ei[NEDGES + e];
        if (d >= 0 && d < NNODES) atomicAdd(&g_deg[d], 1);
    }
}
__global__ void k_dis() {
    int n = blockIdx.x * blockDim.x + threadIdx.x;
    if (n < NNODES) g_dis[n] = rsqrtf((float)(g_deg[n] + 1));
}
__global__ void k_scan1() {
    int t = blockIdx.x * blockDim.x + threadIdx.x;
    const int chunk = (NNODES + 1023) / 1024;
    int base = t * chunk, s = 0;
    for (int i = 0; i < chunk; i++) {
        int n = base + i;
        if (n < NNODES) s += g_deg[n];
    }
    g_tsum[t] = s;
}
__global__ void k_scan2() {
    __shared__ int sh[1024];
    int t = threadIdx.x;
    sh[t] = g_tsum[t];
    __syncthreads();
    for (int off = 1; off < 1024; off <<= 1) {
        int v = (t >= off) ? sh[t - off] : 0;
        __syncthreads();
        sh[t] += v;
        __syncthreads();
    }
    g_tsum[t] = (t == 0) ? 0 : sh[t - 1];
}
__global__ void k_scan3() {
    int t = blockIdx.x * blockDim.x + threadIdx.x;
    const int chunk = (NNODES + 1023) / 1024;
    int base = t * chunk, off = g_tsum[t];
    for (int i = 0; i < chunk; i++) {
        int n = base + i;
        if (n < NNODES) {
            g_rowstart[n] = off;
            off += g_deg[n];
        }
    }
}
__global__ void k_csr(const int* __restrict__ ei) {
    for (int e = blockIdx.x * blockDim.x + threadIdx.x; e < NEDGES;
         e += gridDim.x * blockDim.x) {
        int s = ei[e];
        int d = ei[NEDGES + e];
        if (s < 0 || s >= NNODES || d < 0 || d >= NNODES) continue;
        int pos = g_rowstart[d] + atomicAdd(&g_cursor[d], 1);
        if (pos >= 0 && pos < NEDGES) g_csr[pos] = s;
    }
}

// ---- W[K, Nn] -> W^T split [Nn, K] at dstOff, tiled transpose ----
__global__ void k_cvtwT(const float* __restrict__ W, int Nn, int K, int dstOff) {
    __shared__ float ts[64][65];
    const int tid = threadIdx.x;
    const int n0 = blockIdx.x * 64, k0 = blockIdx.y * 64;
#pragma unroll
    for (int i = 0; i < 16; i++) {
        int idx = tid + i * 256;
        int r = idx >> 6, c = idx & 63;
        ts[r][c] = W[(size_t)(k0 + r) * Nn + n0 + c];
    }
    __syncthreads();
#pragma unroll
    for (int i = 0; i < 8; i++) {
        int idx = tid + i * 256;
        int r = idx >> 5, c2 = (idx & 31) * 2;
        float x0 = ts[c2][r], x1 = ts[c2 + 1][r];
        __nv_bfloat16 h0 = __float2bfloat16(x0);
        __nv_bfloat16 h1 = __float2bfloat16(x1);
        __nv_bfloat16 l0 = __float2bfloat16(x0 - __bfloat162float(h0));
        __nv_bfloat16 l1 = __float2bfloat16(x1 - __bfloat162float(h1));
        size_t off = (size_t)dstOff + (size_t)(n0 + r) * K + k0 + c2;
        uint16_t a0 = *(uint16_t*)&h0, a1 = *(uint16_t*)&h1;
        uint16_t b0 = *(uint16_t*)&l0, b1 = *(uint16_t*)&l1;
        *(uint32_t*)&g_wthi[off] = (uint32_t)a0 | ((uint32_t)a1 << 16);
        *(uint32_t*)&g_wtlo[off] = (uint32_t)b0 | ((uint32_t)b1 << 16);
    }
}

// ---- pre-aggregation: y[d] = dis[d] * sum_{s in N(d)+{d}} x[s]*dis[s]
// 128 threads, float2 per thread, packed bf16x2 stores.
template <int ASEL>
__global__ void k_aggpre(const float* __restrict__ xext) {
    const float2* __restrict__ x2 =
        (ASEL == 0) ? (const float2*)xext : (const float2*)g_x;
    int d = blockIdx.x;
    int f = threadIdx.x;  // 0..127
    float dd = g_dis[d];
    float2 a = x2[(size_t)d * 128 + f];
    float acc0 = a.x * dd, acc1 = a.y * dd;
    int p0 = g_rowstart[d], cnt = g_deg[d];
    int j = 0;
    for (; j + 4 <= cnt; j += 4) {
        int s0 = g_csr[p0 + j],     s1 = g_csr[p0 + j + 1];
        int s2 = g_csr[p0 + j + 2], s3 = g_csr[p0 + j + 3];
        float2 v0 = x2[(size_t)s0 * 128 + f];
        float2 v1 = x2[(size_t)s1 * 128 + f];
        float2 v2 = x2[(size_t)s2 * 128 + f];
        float2 v3 = x2[(size_t)s3 * 128 + f];
        float d0 = g_dis[s0], d1 = g_dis[s1], d2 = g_dis[s2], d3 = g_dis[s3];
        acc0 += v0.x * d0 + v1.x * d1 + v2.x * d2 + v3.x * d3;
        acc1 += v0.y * d0 + v1.y * d1 + v2.y * d2 + v3.y * d3;
    }
    for (; j < cnt; j++) {
        int s = g_csr[p0 + j];
        float2 v = x2[(size_t)s * 128 + f];
        float ds = g_dis[s];
        acc0 += v.x * ds;
        acc1 += v.y * ds;
    }
    float y0 = acc0 * dd, y1 = acc1 * dd;
    __nv_bfloat16 h0 = __float2bfloat16(y0);
    __nv_bfloat16 h1 = __float2bfloat16(y1);
    __nv_bfloat16 l0 = __float2bfloat16(y0 - __bfloat162float(h0));
    __nv_bfloat16 l1 = __float2bfloat16(y1 - __bfloat162float(h1));
    size_t off = (size_t)d * KDIM + 2 * f;
    uint16_t a0 = *(uint16_t*)&h0, a1 = *(uint16_t*)&h1;
    uint16_t b0 = *(uint16_t*)&l0, b1 = *(uint16_t*)&l1;
    *(uint32_t*)&g_ahi[off] = (uint32_t)a0 | ((uint32_t)a1 << 16);
    *(uint32_t*)&g_alo[off] = (uint32_t)b0 | ((uint32_t)b1 << 16);
}

// ================= split-bf16 mma.sync GEMM, 128x128 tile, 3-stage cp.async ===
#define STG_SZ 32768
#define OB     16384
template <int CSEL>
__global__ __launch_bounds__(256, 2) void k_mmagemm(float* __restrict__ Cout,
                                                    int M, int Nn, int K, int wOff,
                                                    const float* __restrict__ bias) {
    extern __shared__ __align__(16) char sm[];     // 3 * STG_SZ
    float* __restrict__ C = (CSEL == 0) ? Cout : (float*)g_x;
    const int tid = threadIdx.x, wid = tid >> 5, lane = tid & 31;
    const int wm = wid & 3, wn = wid >> 2;
    const int bm = blockIdx.x * 128, nb = blockIdx.y * 128;
    const uint32_t sb = smem_u32(sm);

    const int a_row = wm * 32 + (lane & 7) + ((lane >> 3) & 1) * 8;
    const int a_c   = (lane >> 4) & 1;
    const int b_row = wn * 64 + (lane & 7) + ((lane >> 4) & 1) * 8;
    const int b_c   = (lane >> 3) & 1;

    float acc[2][8][4];
#pragma unroll
    for (int mt = 0; mt < 2; mt++)
#pragma unroll
        for (int nt = 0; nt < 8; nt++)
#pragma unroll
            for (int i = 0; i < 4; i++) acc[mt][nt][i] = 0.f;

    auto load_stage = [&](int kc, int s) {
        uint32_t base = sb + s * STG_SZ;
#pragma unroll
        for (int i = 0; i < 4; i++) {
            int idx = tid + i * 256;
            int r = idx >> 3, cc = idx & 7;
            int grow = bm + r;
            int ok = (grow < M);
            int grc = ok ? grow : (M - 1);
            const __nv_bfloat16* src = (cc < 4)
                ? &g_ahi[(size_t)grc * K + kc * 32 + cc * 8]
                : &g_alo[(size_t)grc * K + kc * 32 + (cc - 4) * 8];
            uint32_t dst = base + (r << 7) + ((cc ^ (r & 7)) << 4);
            CP16(dst, src, ok ? 16 : 0);
        }
#pragma unroll
        for (int i = 0; i < 4; i++) {
            int idx = tid + i * 256;
            int r = idx >> 3, cc = idx & 7;
            const __nv_bfloat16* src = (cc < 4)
                ? &g_wthi[(size_t)wOff + (size_t)(nb + r) * K + kc * 32 + cc * 8]
                : &g_wtlo[(size_t)wOff + (size_t)(nb + r) * K + kc * 32 + (cc - 4) * 8];
            uint32_t dst = base + OB + (r << 7) + ((cc ^ (r & 7)) << 4);
            CP16(dst, src, 16);
        }
    };

    const int NKC = K / 32;
    load_stage(0, 0);
    CP_COMMIT();
    load_stage(1, 1);
    CP_COMMIT();

    for (int kc = 0; kc < NKC; kc++) {
        CP_WAIT(1);
        __syncthreads();
        if (kc + 2 < NKC) load_stage(kc + 2, (kc + 2) % 3);
        CP_COMMIT();

        uint32_t stg = sb + (kc % 3) * STG_SZ;
#pragma unroll
        for (int ks = 0; ks < 2; ks++) {
            uint32_t ah[2][4], al[2][4], bh[4][4], bl[4][4];
            int ach = ks * 2 + a_c;
            int bch = ks * 2 + b_c;
#pragma unroll
            for (int mt = 0; mt < 2; mt++) {
                int row = a_row + mt * 16;
                uint32_t rb_ = stg + (row << 7);
                LDSM4(ah[mt], rb_ + ((ach ^ (row & 7)) << 4));
                LDSM4(al[mt], rb_ + (((ach + 4) ^ (row & 7)) << 4));
            }
#pragma unroll
            for (int p = 0; p < 4; p++) {
                int row = b_row + p * 16;
                uint32_t rb_ = stg + OB + (row << 7);
                LDSM4(bh[p], rb_ + ((bch ^ (row & 7)) << 4));
                LDSM4(bl[p], rb_ + (((bch + 4) ^ (row & 7)) << 4));
            }
#pragma unroll
            for (int mt = 0; mt < 2; mt++)
#pragma unroll
                for (int nt = 0; nt < 8; nt++) {
                    int p = nt >> 1, s2 = (nt & 1) * 2;
                    MMA_BF16(acc[mt][nt], ah[mt], bh[p][s2], bh[p][s2 + 1]);
                    MMA_BF16(acc[mt][nt], ah[mt], bl[p][s2], bl[p][s2 + 1]);
                    MMA_BF16(acc[mt][nt], al[mt], bh[p][s2], bh[p][s2 + 1]);
                }
        }
        __syncthreads();
    }

#pragma unroll
    for (int mt = 0; mt < 2; mt++) {
        int r0 = bm + wm * 32 + mt * 16 + (lane >> 2);
        int r1 = r0 + 8;
#pragma unroll
        for (int nt = 0; nt < 8; nt++) {
            int col = nb + wn * 64 + nt * 8 + (lane & 3) * 2;
            float bb0 = bias[col], bb1 = bias[col + 1];
            if (r0 < M) {
                float2 v = make_float2(fmaxf(acc[mt][nt][0] + bb0, 0.f),
                                       fmaxf(acc[mt][nt][1] + bb1, 0.f));
                *(float2*)&C[(size_t)r0 * Nn + col] = v;
            }
            if (r1 < M) {
                float2 v = make_float2(fmaxf(acc[mt][nt][2] + bb0, 0.f),
                                       fmaxf(acc[mt][nt][3] + bb1, 0.f));
                *(float2*)&C[(size_t)r1 * Nn + col] = v;
            }
        }
    }
}

// ================= pooling (gate fused) =================
__global__ void k_gstart(const int* __restrict__ batch) {
    for (int n = blockIdx.x * blockDim.x + threadIdx.x; n < NNODES;
         n += gridDim.x * blockDim.x) {
        int b = batch[n];
        if (b < 0) b = 0;
        if (b >= NGRAPH) b = NGRAPH - 1;
        int prev = -1;
        if (n) {
            prev = batch[n - 1];
            if (prev < 0) prev = 0;
            if (prev >= NGRAPH) prev = NGRAPH - 1;
        }
        for (int g = prev + 1; g <= b; g++) g_gstart[g] = n;
        if (n == NNODES - 1)
            for (int g = b + 1; g <= NGRAPH; g++) g_gstart[g] = NNODES;
    }
}

// block per graph: compute gates chunk-wise (warp dot-products), then
// accumulate weighted-sum + max; emit head A operand (bf16 hi/lo, K=1024).
__global__ void k_poolgate(const float* __restrict__ pw,
                           const float* __restrict__ pb) {
    __shared__ float spw[512];
    __shared__ float sg[64];
    int g = blockIdx.x, tid = threadIdx.x, lane = tid & 31, wid = tid >> 5;
    for (int i = tid; i < 512; i += 256) spw[i] = pw[i];
    float pbv = pb[0];
    __syncthreads();
    int s = g_gstart[g], e = g_gstart[g + 1];
    float ws0 = 0.f, ws1 = 0.f, mx0 = 0.f, mx1 = 0.f;
    for (int c = s; c < e; c += 64) {
        int nc = min(64, e - c);
        for (int j = wid; j < nc; j += 8) {
            const float* row = &g_x[(size_t)(c + j) * 512];
            float dt = 0.f;
#pragma unroll
            for (int i = 0; i < 16; i++) dt += row[lane + 32 * i] * spw[lane + 32 * i];
#pragma unroll
            for (int o = 16; o; o >>= 1) dt += __shfl_xor_sync(0xFFFFFFFFu, dt, o);
            if (lane == 0) sg[j] = 1.f / (1.f + expf(-(dt + pbv)));
        }
        __syncthreads();
        for (int j = 0; j < nc; j++) {
            float w = sg[j];
            float v0 = g_x[(size_t)(c + j) * 512 + tid];
            float v1 = g_x[(size_t)(c + j) * 512 + tid + 256];
            ws0 += v0 * w;
            ws1 += v1 * w;
            mx0 = fmaxf(mx0, v0);
            mx1 = fmaxf(mx1, v1);
        }
        __syncthreads();
    }
    size_t base = (size_t)g * 1024;
    float vs[4] = {ws0, ws1, mx0, mx1};
    int   cs[4] = {tid, tid + 256, 512 + tid, 768 + tid};
#pragma unroll
    for (int i = 0; i < 4; i++) {
        __nv_bfloat16 h = __float2bfloat16(vs[i]);
        g_ahi[base + cs[i]] = h;
        g_alo[base + cs[i]] = __float2bfloat16(vs[i] - __bfloat162float(h));
    }
}

extern "C" void kernel_launch(void* const* d_in, const int* in_sizes, int n_in,
                              void* d_out, int out_size) {
    const float* xin   = (const float*)d_in[0];
    const int*   ei    = (const int*)d_in[1];
    const int*   batch = (const int*)d_in[2];
    const float* W1 = (const float*)d_in[3];
    const float* b1 = (const float*)d_in[4];
    const float* W2 = (const float*)d_in[5];
    const float* b2 = (const float*)d_in[6];
    const float* W3 = (const float*)d_in[7];
    const float* b3 = (const float*)d_in[8];
    const float* pw = (const float*)d_in[9];
    const float* pb = (const float*)d_in[10];
    const float* Wo = (const float*)d_in[11];
    const float* bo = (const float*)d_in[12];
    float* out = (float*)d_out;

    cudaFuncSetAttribute(k_mmagemm<0>, cudaFuncAttributeMaxDynamicSharedMemorySize,
                         3 * STG_SZ);
    cudaFuncSetAttribute(k_mmagemm<1>, cudaFuncAttributeMaxDynamicSharedMemorySize,
                         3 * STG_SZ);

    // graph structure + weight conversions
    k_zero<<<196, 256>>>();
    k_deg<<<512, 256>>>(ei);
    k_cvtwT<<<dim3(4, 4), 256>>>(W1, 256, KDIM, WOFF1);
    k_cvtwT<<<dim3(4, 4), 256>>>(W2, 256, KDIM, WOFF2);
    k_cvtwT<<<dim3(8, 4), 256>>>(W3, 512, KDIM, WOFF3);
    k_cvtwT<<<dim3(32, 16), 256>>>(Wo, 2048, 1024, WOFF0);
    k_dis<<<(NNODES + 255) / 256, 256>>>();
    k_scan1<<<4, 256>>>();
    k_scan2<<<1, 1024>>>();
    k_scan3<<<4, 256>>>();
    k_csr<<<512, 256>>>(ei);

    const int MBLK = (NNODES + 127) / 128;  // 391

    // layer 1
    k_aggpre<0><<<NNODES, 128>>>(xin);
    k_mmagemm<1><<<dim3(MBLK, 2), 256, 3 * STG_SZ>>>(nullptr, NNODES, 256, KDIM,
                                                     WOFF1, b1);
    // layer 2
    k_aggpre<1><<<NNODES, 128>>>(nullptr);
    k_mmagemm<1><<<dim3(MBLK, 2), 256, 3 * STG_SZ>>>(nullptr, NNODES, 256, KDIM,
                                                     WOFF2, b2);
    // layer 3
    k_aggpre<1><<<NNODES, 128>>>(nullptr);
    k_mmagemm<1><<<dim3(MBLK, 4), 256, 3 * STG_SZ>>>(nullptr, NNODES, 512, KDIM,
                                                     WOFF3, b3);

    // pooling (gate fused; emits head A operand split)
    k_gstart<<<196, 256>>>(batch);
    k_poolgate<<<NGRAPH, 256>>>(pw, pb);

    // head: [512,1024] @ [1024,2048] + bias, relu -> out
    k_mmagemm<0><<<dim3(4, 16), 256, 3 * STG_SZ>>>(out, NGRAPH, 2048, 1024,
                                                   WOFF0, bo);
}